// round 13
// baseline (speedup 1.0000x reference)
#include <cuda_runtime.h>

#define BB 4
#define CC 512
#define TT 1024
#define HH 8
#define DD 64
#define WW 4

typedef unsigned long long u64;

// ---------------- device scratch (no runtime allocation allowed) ----------------
__device__ float g_Q [BB*CC*TT];   // [B][C][T]
__device__ float g_K [BB*CC*TT];
__device__ float g_V [BB*CC*TT];
__device__ float g_AO[BB*CC*TT];

// ---------------- packed f32x2 helpers ----------------
__device__ __forceinline__ u64 pk2(float x, float y) {
    u64 r; asm("mov.b64 %0, {%1, %2};" : "=l"(r) : "f"(x), "f"(y)); return r;
}
__device__ __forceinline__ u64 dup2(float x) {
    u64 r; asm("mov.b64 %0, {%1, %1};" : "=l"(r) : "f"(x)); return r;
}
__device__ __forceinline__ void fma2(u64 &d, u64 a, u64 b) {
    asm("fma.rn.f32x2 %0, %1, %2, %0;" : "+l"(d) : "l"(a), "l"(b));
}
__device__ __forceinline__ void mul2(u64 &d, u64 a) {
    asm("mul.rn.f32x2 %0, %0, %1;" : "+l"(d) : "l"(a));
}
__device__ __forceinline__ float2 upk2(u64 v) {
    float2 f; asm("mov.b64 {%0, %1}, %2;" : "=f"(f.x), "=f"(f.y) : "l"(v)); return f;
}

// =====================================================================
// 128x128x16 SGEMM, double-buffered smem, f32x2 core, split-key B cols.
// (measured: qkv ~146-148us / outproj ~50us — unchanged)
// =====================================================================
__device__ __forceinline__ void gemm128(const float* __restrict__ Xb,
                                        const float* __restrict__ Wm,
                                        const float* __restrict__ bias,
                                        float* __restrict__ Yb,
                                        int o0, int t0)
{
    __shared__ float As[2][16][132];
    __shared__ float Bs[2][16][132];

    const int tid = threadIdx.x;
    const int ty  = tid >> 4, tx = tid & 15;
    const int am  = tid >> 1;
    const int ak  = (tid & 1) << 3;
    const int bkr = tid >> 4;
    const int bn  = (tid & 15) << 3;

    const float* wp = Wm + (size_t)(o0 + am) * CC + ak;
    const float* xp = Xb + (size_t)bkr * TT + t0 + bn;

    u64 acc[4][8];
#pragma unroll
    for (int i = 0; i < 4; i++)
#pragma unroll
        for (int j = 0; j < 8; j++) acc[i][j] = 0ull;

    {
        float4 a0 = *(const float4*)(wp);
        float4 a1 = *(const float4*)(wp + 4);
        float4 b0 = *(const float4*)(xp);
        float4 b1 = *(const float4*)(xp + 4);
        As[0][ak+0][am]=a0.x; As[0][ak+1][am]=a0.y; As[0][ak+2][am]=a0.z; As[0][ak+3][am]=a0.w;
        As[0][ak+4][am]=a1.x; As[0][ak+5][am]=a1.y; As[0][ak+6][am]=a1.z; As[0][ak+7][am]=a1.w;
        *(float4*)&Bs[0][bkr][bn]     = b0;
        *(float4*)&Bs[0][bkr][bn + 4] = b1;
    }
    __syncthreads();

    const int NCH = CC / 16;
    for (int ch = 0; ch < NCH; ch++) {
        const int cur = ch & 1;
        float4 na0, na1, nb0, nb1;
        if (ch + 1 < NCH) {
            const float* wq = wp + (ch + 1) * 16;
            const float* xq = xp + (size_t)(ch + 1) * 16 * TT;
            na0 = *(const float4*)(wq);
            na1 = *(const float4*)(wq + 4);
            nb0 = *(const float4*)(xq);
            nb1 = *(const float4*)(xq + 4);
        }

#pragma unroll
        for (int k = 0; k < 16; k++) {
            float4 fa0 = *(const float4*)&As[cur][k][ty * 8];
            float4 fa1 = *(const float4*)&As[cur][k][ty * 8 + 4];
            float4 fb0 = *(const float4*)&Bs[cur][k][tx * 4];
            float4 fb1 = *(const float4*)&Bs[cur][k][64 + tx * 4];
            u64 ap[4] = { pk2(fa0.x, fa0.y), pk2(fa0.z, fa0.w),
                          pk2(fa1.x, fa1.y), pk2(fa1.z, fa1.w) };
            float bb[8] = { fb0.x, fb0.y, fb0.z, fb0.w, fb1.x, fb1.y, fb1.z, fb1.w };
#pragma unroll
            for (int j = 0; j < 8; j++) {
                u64 bd = dup2(bb[j]);
#pragma unroll
                for (int i = 0; i < 4; i++) fma2(acc[i][j], ap[i], bd);
            }
        }

        if (ch + 1 < NCH) {
            const int nxt = cur ^ 1;
            As[nxt][ak+0][am]=na0.x; As[nxt][ak+1][am]=na0.y; As[nxt][ak+2][am]=na0.z; As[nxt][ak+3][am]=na0.w;
            As[nxt][ak+4][am]=na1.x; As[nxt][ak+5][am]=na1.y; As[nxt][ak+6][am]=na1.z; As[nxt][ak+7][am]=na1.w;
            *(float4*)&Bs[nxt][bkr][bn]     = nb0;
            *(float4*)&Bs[nxt][bkr][bn + 4] = nb1;
            __syncthreads();
        }
    }

#pragma unroll
    for (int i = 0; i < 4; i++) {
        const int o = o0 + ty * 8 + 2 * i;
        const float bl = bias[o], bh = bias[o + 1];
        float lo[8], hi[8];
#pragma unroll
        for (int j = 0; j < 8; j++) {
            float2 e = upk2(acc[i][j]);
            lo[j] = e.x + bl; hi[j] = e.y + bh;
        }
        float* y0a = Yb + (size_t)o * TT + t0 + tx * 4;
        float* y0b = Yb + (size_t)o * TT + t0 + 64 + tx * 4;
        *(float4*)y0a        = make_float4(lo[0], lo[1], lo[2], lo[3]);
        *(float4*)y0b        = make_float4(lo[4], lo[5], lo[6], lo[7]);
        *(float4*)(y0a + TT) = make_float4(hi[0], hi[1], hi[2], hi[3]);
        *(float4*)(y0b + TT) = make_float4(hi[4], hi[5], hi[6], hi[7]);
    }
}

__global__ void __launch_bounds__(256, 2)
qkv_kernel(const float* __restrict__ x,
           const float* __restrict__ Wq, const float* __restrict__ bq,
           const float* __restrict__ Wk, const float* __restrict__ bk,
           const float* __restrict__ Wv, const float* __restrict__ bv)
{
    const int z = blockIdx.z;
    const int m = z % 3;
    const int b = z / 3;
    const float* Wm = (m == 0) ? Wq : (m == 1) ? Wk : Wv;
    const float* bm = (m == 0) ? bq : (m == 1) ? bk : bv;
    float* dst      = (m == 0) ? g_Q : (m == 1) ? g_K : g_V;
    gemm128(x + (size_t)b * CC * TT, Wm, bm, dst + (size_t)b * CC * TT,
            blockIdx.y << 7, blockIdx.x << 7);
}

__global__ void __launch_bounds__(256, 2)
outproj_kernel(const float* __restrict__ Wo, const float* __restrict__ bo,
               float* __restrict__ out)
{
    const int b = blockIdx.z;
    gemm128(g_AO + (size_t)b * CC * TT, Wo, bo, out + (size_t)b * CC * TT,
            blockIdx.y << 7, blockIdx.x << 7);
}

// =====================================================================
// Flash attention v6: R11 geometry (64-row CTA, 64-key tiles, 4x4 micro)
// at 3 CTAs/SM. smem trimmed to 73.5KB by aliasing ek onto Ps (ek is
// prologue-only; Ps first written two syncs later).
// smem float offsets:
//   QsT   0      [64][68]
//   KsT   4352   [64][68]
//   Vs    8704   [64][68]
//   Ps    13056  [64][68]   (ek[9][64] aliased here during prologue)
//   ev    17408  [9][64]
//   qrel  17984  [64][12]
//   msk   18752  int[64]
// total 18816 floats = 75264 B; 3 x 75264 = 220.5KB <= 228KB/SM
// =====================================================================
#define ATTN_SMEM_BYTES 75264

__global__ void __launch_bounds__(256, 3)
attn_kernel(const int* __restrict__ maskp,
            const float* __restrict__ emk,
            const float* __restrict__ emv)
{
    extern __shared__ float sf[];
    float* QsT  = sf;             // stride 68
    float* KsT  = sf + 4352;      // stride 68
    float* Vs   = sf + 8704;      // stride 68
    float* Ps   = sf + 13056;     // stride 68
    float* ekA  = sf + 13056;     // prologue alias of Ps: [9][64]
    float* ev   = sf + 17408;     // [9][64]
    float* qrel = sf + 17984;     // stride 12
    int*   msk  = (int*)(sf + 18752);

    const int tid = threadIdx.x;
    const int ty  = tid >> 4;
    const int tx  = tid & 15;
    const int bh  = blockIdx.y;
    const int b   = bh >> 3;
    const int h   = bh & 7;
    const int t0  = blockIdx.x << 6;

    const float* Qg = g_Q + ((size_t)b * CC + h * DD) * TT;
    const float* Kg = g_K + ((size_t)b * CC + h * DD) * TT;
    const float* Vg = g_V + ((size_t)b * CC + h * DD) * TT;

    // V register-gather mapping: thread owns one key, 4 dim-groups
    const int vkey = tid & 63;
    const int vg0  = tid >> 6;    // 0..3

    // prologue: ek (into Ps alias), ev, Q (pre-scaled 1/8)
    for (int idx = tid; idx < 9 * DD; idx += 256) {
        ekA[idx] = emk[idx];
        ev[idx]  = emv[idx];
    }
    for (int idx = tid; idx < DD * 16; idx += 256) {
        const int j  = idx >> 4;
        const int r4 = (idx & 15) * 4;
        float4 q = *(const float4*)&Qg[(size_t)j * TT + t0 + r4];
        q.x *= 0.125f; q.y *= 0.125f; q.z *= 0.125f; q.w *= 0.125f;
        *(float4*)&QsT[j * 68 + r4] = q;
    }
    __syncthreads();

    // qrel[r][e] = (Q/8) . ek[e]   (reads the Ps-alias; done before tile loop)
    for (int idx = tid; idx < 64 * 9; idx += 256) {
        const int r = idx & 63;
        const int e = idx >> 6;
        float s = 0.0f;
#pragma unroll 8
        for (int j = 0; j < DD; j++) s += QsT[j * 68 + r] * ekA[e * 64 + j];
        qrel[r * 12 + e] = s;
    }

    float mrun[4], lrun[4];
    u64 O2[2][4];
#pragma unroll
    for (int i = 0; i < 4; i++) { mrun[i] = -1e30f; lrun[i] = 0.0f; }
#pragma unroll
    for (int p = 0; p < 2; p++)
#pragma unroll
        for (int j = 0; j < 4; j++) O2[p][j] = 0ull;

    for (int c0 = 0; c0 < TT; c0 += 64) {
        __syncthreads();   // qrel written (1st iter) / prev PV+band reads done
        // K tile: dim-major float4 (coalesced, conflict-free)
        for (int idx = tid; idx < DD * 16; idx += 256) {
            const int j  = idx >> 4;
            const int c4 = (idx & 15) * 4;
            *(float4*)&KsT[j * 68 + c4] = *(const float4*)&Kg[(size_t)j * TT + c0 + c4];
        }
        // V tile: register-gather transpose -> Vs[key][dim]
#pragma unroll
        for (int g = 0; g < 4; g++) {
            const int gg = vg0 + g * 4;
            const float* vp = Vg + (size_t)(gg * 4) * TT + c0 + vkey;
            float4 v4;
            v4.x = vp[0 * TT];
            v4.y = vp[1 * TT];
            v4.z = vp[2 * TT];
            v4.w = vp[3 * TT];
            *(float4*)&Vs[vkey * 68 + gg * 4] = v4;
        }
        if (tid < 64) msk[tid] = maskp[b * TT + c0 + tid];
        __syncthreads();

        // ---- S = (Q/8) K^T ----
        u64 sv2[2][4];
#pragma unroll
        for (int p = 0; p < 2; p++)
#pragma unroll
            for (int j = 0; j < 4; j++) sv2[p][j] = 0ull;

#pragma unroll 8
        for (int j = 0; j < DD; j++) {
            float4 a  = *(const float4*)&QsT[j * 68 + ty * 4];
            float4 k4 = *(const float4*)&KsT[j * 68 + tx * 4];
            u64 ap0 = pk2(a.x, a.y);
            u64 ap1 = pk2(a.z, a.w);
            u64 bd;
            bd = dup2(k4.x); fma2(sv2[0][0], ap0, bd); fma2(sv2[1][0], ap1, bd);
            bd = dup2(k4.y); fma2(sv2[0][1], ap0, bd); fma2(sv2[1][1], ap1, bd);
            bd = dup2(k4.z); fma2(sv2[0][2], ap0, bd); fma2(sv2[1][2], ap1, bd);
            bd = dup2(k4.w); fma2(sv2[0][3], ap0, bd); fma2(sv2[1][3], ap1, bd);
        }

        float sv[4][4];
#pragma unroll
        for (int jj = 0; jj < 4; jj++) {
            float2 e0 = upk2(sv2[0][jj]);
            float2 e1 = upk2(sv2[1][jj]);
            sv[0][jj] = e0.x; sv[1][jj] = e0.y;
            sv[2][jj] = e1.x; sv[3][jj] = e1.y;
        }

        // ---- band score + mask ----
#pragma unroll
        for (int i = 0; i < 4; i++) {
            const int t = t0 + ty * 4 + i;
#pragma unroll
            for (int jj = 0; jj < 4; jj++) {
                const int s = c0 + tx * 4 + jj;
                const int e = s - t + WW;
                float v = sv[i][jj];
                if (e >= 0 && e <= 2 * WW) v += qrel[(ty * 4 + i) * 12 + e];
                if (msk[tx * 4 + jj] == 0) v = -10000.0f;
                sv[i][jj] = v;
            }
        }

        // ---- online softmax ----
        float f[4];
#pragma unroll
        for (int i = 0; i < 4; i++) {
            float tm = fmaxf(fmaxf(sv[i][0], sv[i][1]), fmaxf(sv[i][2], sv[i][3]));
#pragma unroll
            for (int o = 1; o < 16; o <<= 1)
                tm = fmaxf(tm, __shfl_xor_sync(0xffffffffu, tm, o));
            const float mn = fmaxf(mrun[i], tm);
            f[i] = __expf(mrun[i] - mn);
            mrun[i] = mn;
        }
#pragma unroll
        for (int i = 0; i < 4; i++) {
            float rs = 0.0f;
#pragma unroll
            for (int jj = 0; jj < 4; jj++) {
                const float p = __expf(sv[i][jj] - mrun[i]);
                sv[i][jj] = p;
                rs += p;
            }
#pragma unroll
            for (int o = 1; o < 16; o <<= 1)
                rs += __shfl_xor_sync(0xffffffffu, rs, o);
            lrun[i] = lrun[i] * f[i] + rs;
        }
        {
            u64 f01 = pk2(f[0], f[1]);
            u64 f23 = pk2(f[2], f[3]);
#pragma unroll
            for (int jj = 0; jj < 4; jj++) { mul2(O2[0][jj], f01); mul2(O2[1][jj], f23); }
        }

#pragma unroll
        for (int i = 0; i < 4; i++)
#pragma unroll
            for (int jj = 0; jj < 4; jj++)
                Ps[(ty * 4 + i) * 68 + tx * 4 + jj] = sv[i][jj];
        __syncthreads();

        // ---- O += P V ----
#pragma unroll 4
        for (int c = 0; c < 64; c += 4) {
            float P0[4], P1[4], P2[4], P3[4];
            *(float4*)P0 = *(const float4*)&Ps[(ty * 4 + 0) * 68 + c];
            *(float4*)P1 = *(const float4*)&Ps[(ty * 4 + 1) * 68 + c];
            *(float4*)P2 = *(const float4*)&Ps[(ty * 4 + 2) * 68 + c];
            *(float4*)P3 = *(const float4*)&Ps[(ty * 4 + 3) * 68 + c];
#pragma unroll
            for (int cc = 0; cc < 4; cc++) {
                float4 v = *(const float4*)&Vs[(c + cc) * 68 + tx * 4];
                u64 pp0 = pk2(P0[cc], P1[cc]);
                u64 pp1 = pk2(P2[cc], P3[cc]);
                u64 vd;
                vd = dup2(v.x); fma2(O2[0][0], pp0, vd); fma2(O2[1][0], pp1, vd);
                vd = dup2(v.y); fma2(O2[0][1], pp0, vd); fma2(O2[1][1], pp1, vd);
                vd = dup2(v.z); fma2(O2[0][2], pp0, vd); fma2(O2[1][2], pp1, vd);
                vd = dup2(v.w); fma2(O2[0][3], pp0, vd); fma2(O2[1][3], pp1, vd);
            }
        }

        // ---- band value term ----
        const int dc = c0 - t0;
        if (dc >= -64 && dc <= 64) {
#pragma unroll
            for (int e = 0; e <= 2 * WW; e++) {
                float4 e4 = *(const float4*)&ev[e * 64 + tx * 4];
                const int cb = t0 + ty * 4 + e - WW - c0;
                float pr[4];
#pragma unroll
                for (int i = 0; i < 4; i++) {
                    const int c = cb + i;
                    pr[i] = (c >= 0 && c < 64) ? Ps[(ty * 4 + i) * 68 + c] : 0.0f;
                }
                u64 pp0 = pk2(pr[0], pr[1]);
                u64 pp1 = pk2(pr[2], pr[3]);
                u64 vd;
                vd = dup2(e4.x); fma2(O2[0][0], pp0, vd); fma2(O2[1][0], pp1, vd);
                vd = dup2(e4.y); fma2(O2[0][1], pp0, vd); fma2(O2[1][1], pp1, vd);
                vd = dup2(e4.z); fma2(O2[0][2], pp0, vd); fma2(O2[1][2], pp1, vd);
                vd = dup2(e4.w); fma2(O2[0][3], pp0, vd); fma2(O2[1][3], pp1, vd);
            }
        }
    }

    // ---- epilogue: normalize, stage transposed, coalesced store ----
    __syncthreads();
    {
        const float i0 = 1.0f / lrun[0], i1 = 1.0f / lrun[1];
        const float i2 = 1.0f / lrun[2], i3 = 1.0f / lrun[3];
#pragma unroll
        for (int jj = 0; jj < 4; jj++) {
            float2 e0 = upk2(O2[0][jj]);
            float2 e1 = upk2(O2[1][jj]);
            Ps[(tx * 4 + jj) * 68 + ty * 4 + 0] = e0.x * i0;
            Ps[(tx * 4 + jj) * 68 + ty * 4 + 1] = e0.y * i1;
            Ps[(tx * 4 + jj) * 68 + ty * 4 + 2] = e1.x * i2;
            Ps[(tx * 4 + jj) * 68 + ty * 4 + 3] = e1.y * i3;
        }
    }
    __syncthreads();
    float* AOg = g_AO + ((size_t)b * CC + h * DD) * TT;
    for (int idx = tid; idx < DD * 16; idx += 256) {
        const int j  = idx >> 4;
        const int r4 = (idx & 15) * 4;
        *(float4*)&AOg[(size_t)j * TT + t0 + r4] = *(const float4*)&Ps[j * 68 + r4];
    }
}

// =====================================================================
extern "C" void kernel_launch(void* const* d_in, const int* in_sizes, int n_in,
                              void* d_out, int out_size)
{
    (void)in_sizes; (void)n_in; (void)out_size;
    const float* x    = (const float*)d_in[0];
    const int*   mask = (const int*)  d_in[1];
    const float* Wq   = (const float*)d_in[2];
    const float* bq   = (const float*)d_in[3];
    const float* Wk   = (const float*)d_in[4];
    const float* bk   = (const float*)d_in[5];
    const float* Wv   = (const float*)d_in[6];
    const float* bv   = (const float*)d_in[7];
    const float* Wo   = (const float*)d_in[8];
    const float* bo   = (const float*)d_in[9];
    const float* emk  = (const float*)d_in[10];
    const float* emv  = (const float*)d_in[11];
    float* out = (float*)d_out;

    cudaFuncSetAttribute(attn_kernel,
                         cudaFuncAttributeMaxDynamicSharedMemorySize,
                         ATTN_SMEM_BYTES);

    dim3 g1(TT / 128, CC / 128, BB * 3);
    qkv_kernel<<<g1, 256>>>(x, Wq, bq, Wk, bk, Wv, bv);

    dim3 g2(TT / 64, BB * HH);
    attn_kernel<<<g2, 256, ATTN_SMEM_BYTES>>>(mask, emk, emv);

    dim3 g3(TT / 128, CC / 128, BB);
    outproj_kernel<<<g3, 256>>>(Wo, bo, out);
}